// round 1
// baseline (speedup 1.0000x reference)
#include <cuda_runtime.h>
#include <math.h>

// Problem constants (fixed by the reference)
#define Tn   4096
#define Hn   2048
#define En   32
#define Kn   4
#define Fn   1408
#define F2n  2816
#define FSn  5632
#define FS2n 11264
#define RPAD (Tn*Kn + En*128)   // 20480: expert segments aligned to 128 rows

// -------------------- device scratch (no allocations allowed) --------------------
__device__ float g_gu  [(size_t)RPAD * F2n];   // expert gate_up output
__device__ float g_act [(size_t)RPAD * Fn];    // expert SwiGLU activation
__device__ float g_eout[(size_t)RPAD * Hn];    // expert down output
__device__ float g_sgu [(size_t)Tn * FS2n];    // shared gate_up output
__device__ float g_sact[(size_t)Tn * FSn];     // shared SwiGLU activation
__device__ float g_sout[(size_t)Tn * Hn];      // shared down output
__device__ int   g_row_token[RPAD];            // expanded-row -> source token (-1 = padding)
__device__ int   g_row_id[Tn*Kn];              // (t,k) -> expanded row
__device__ float g_rw[Tn*Kn];                  // routing weight per (t,k)
__device__ float g_gate[Tn];                   // sigmoid shared-expert gate per token
__device__ int   g_cnt[En];
__device__ int   g_off[En+1];                  // 128-aligned expert segment offsets
__device__ int   g_pos[Tn*Kn];
__device__ int   g_eidx[Tn*Kn];

// -------------------- init: zero counters, poison row_token --------------------
__global__ void k_init() {
    int i = blockIdx.x * blockDim.x + threadIdx.x;
    if (i < En)   g_cnt[i] = 0;
    if (i < RPAD) g_row_token[i] = -1;
}

// -------------------- router: logits -> softmax -> top-4, + shared gate dot ----
__global__ void k_router(const float* __restrict__ hs,
                         const float* __restrict__ rw,
                         const float* __restrict__ gw)
{
    __shared__ float sh[Hn];
    __shared__ float slog[En];
    __shared__ float sred[128];
    int t = blockIdx.x;
    const float* hrow = hs + (size_t)t * Hn;
    for (int i = threadIdx.x; i < Hn; i += 128) sh[i] = hrow[i];
    __syncthreads();

    int warp = threadIdx.x >> 5, lane = threadIdx.x & 31;
    #pragma unroll
    for (int eo = 0; eo < 8; eo++) {
        int e = (warp << 3) + eo;
        const float* w = rw + (size_t)e * Hn;
        float acc = 0.f;
        for (int h = lane; h < Hn; h += 32) acc = fmaf(sh[h], w[h], acc);
        #pragma unroll
        for (int o = 16; o; o >>= 1) acc += __shfl_down_sync(0xffffffffu, acc, o);
        if (lane == 0) slog[e] = acc;
    }
    // shared-expert gate: dot(hidden, gate_w)
    float g = 0.f;
    for (int h = threadIdx.x; h < Hn; h += 128) g = fmaf(sh[h], gw[h], g);
    sred[threadIdx.x] = g;
    __syncthreads();
    for (int s = 64; s; s >>= 1) {
        if (threadIdx.x < s) sred[threadIdx.x] += sred[threadIdx.x + s];
        __syncthreads();
    }

    if (threadIdx.x == 0) {
        g_gate[t] = 1.f / (1.f + expf(-sred[0]));
        float mx = slog[0];
        for (int e = 1; e < En; e++) mx = fmaxf(mx, slog[e]);
        float p[En]; float sum = 0.f;
        for (int e = 0; e < En; e++) { p[e] = expf(slog[e] - mx); sum += p[e]; }
        float inv = 1.f / sum;
        for (int k = 0; k < Kn; k++) {
            int best = 0; float bp = p[0];
            for (int e = 1; e < En; e++) if (p[e] > bp) { bp = p[e]; best = e; }  // strict > : lowest index wins ties (matches jax top_k)
            int i4 = t * Kn + k;
            g_eidx[i4] = best;
            g_rw[i4]   = bp * inv;
            g_pos[i4]  = atomicAdd(&g_cnt[best], 1);
            p[best] = -1.f;
        }
    }
}

// -------------------- exclusive scan with 128-row alignment --------------------
__global__ void k_scan() {
    int o = 0; g_off[0] = 0;
    for (int e = 0; e < En; e++) { o += ((g_cnt[e] + 127) & ~127); g_off[e+1] = o; }
}

// -------------------- scatter: assign (t,k) -> expanded row --------------------
__global__ void k_scatter() {
    int i = blockIdx.x * blockDim.x + threadIdx.x;
    if (i >= Tn * Kn) return;
    int e = g_eidx[i];
    int row = g_off[e] + g_pos[i];
    g_row_token[row] = i >> 2;
    g_row_id[i] = row;
}

// -------------------- tiled fp32 GEMM, 128x128x8, 256 threads, 8x8/thread ------
// MODE 0: plain (A row-major [M,Kdim], row0 from blockIdx.y)
// MODE 1: grouped + gather A rows via g_row_token (A = hidden)
// MODE 2: grouped, direct A rows (A = g_act)
template<int MODE>
__global__ void __launch_bounds__(256) k_gemm(const float* __restrict__ A,
                                              const float* __restrict__ B,
                                              float* __restrict__ C,
                                              int Kdim, int N)
{
    __shared__ __align__(16) float As[8][132];
    __shared__ __align__(16) float Bs[8][128];
    __shared__ int toks[128];
    __shared__ int sE;
    const int row0 = blockIdx.y * 128;
    const int col0 = blockIdx.x * 128;
    const int tid  = threadIdx.x;

    if (MODE != 0) {
        if (tid == 0) {
            int ee = -1;
            if (row0 < g_off[En]) {
                int e = 0;
                while (row0 >= g_off[e+1]) e++;
                ee = (row0 < g_off[e] + g_cnt[e]) ? e : -1;   // all-padding tile -> skip
            }
            sE = ee;
        }
        __syncthreads();
        int e = sE;
        if (e < 0) return;
        B += (size_t)e * Kdim * N;
        if (MODE == 1) {
            if (tid < 128) toks[tid] = g_row_token[row0 + tid];
            __syncthreads();
        }
    }

    const int arow = tid >> 1;
    const int acol = (tid & 1) << 2;
    const int brow = tid >> 5;
    const int bcol = (tid & 31) << 2;

    const float* aptr;
    bool avalid = true;
    if (MODE == 1) {
        int tok = toks[arow];
        avalid = (tok >= 0);
        aptr = A + (size_t)(avalid ? tok : 0) * Kdim + acol;
    } else {
        aptr = A + (size_t)(row0 + arow) * Kdim + acol;
    }
    const float* bptr = B + (size_t)brow * N + col0 + bcol;

    const int tm = (tid >> 4) << 3;
    const int tn = (tid & 15) << 3;

    float acc[8][8];
    #pragma unroll
    for (int i = 0; i < 8; i++)
        #pragma unroll
        for (int j = 0; j < 8; j++) acc[i][j] = 0.f;

    for (int k0 = 0; k0 < Kdim; k0 += 8) {
        float4 av = avalid ? *(const float4*)aptr : make_float4(0.f,0.f,0.f,0.f);
        float4 bv = *(const float4*)bptr;
        __syncthreads();
        As[acol+0][arow] = av.x; As[acol+1][arow] = av.y;
        As[acol+2][arow] = av.z; As[acol+3][arow] = av.w;
        *(float4*)&Bs[brow][bcol] = bv;
        __syncthreads();
        #pragma unroll
        for (int kk = 0; kk < 8; kk++) {
            float a[8], b[8];
            *(float4*)(a)   = *(const float4*)&As[kk][tm];
            *(float4*)(a+4) = *(const float4*)&As[kk][tm+4];
            *(float4*)(b)   = *(const float4*)&Bs[kk][tn];
            *(float4*)(b+4) = *(const float4*)&Bs[kk][tn+4];
            #pragma unroll
            for (int i = 0; i < 8; i++)
                #pragma unroll
                for (int j = 0; j < 8; j++)
                    acc[i][j] = fmaf(a[i], b[j], acc[i][j]);
        }
        aptr += 8;
        bptr += (size_t)8 * N;
    }

    #pragma unroll
    for (int i = 0; i < 8; i++) {
        float* cp = C + (size_t)(row0 + tm + i) * N + col0 + tn;
        *(float4*)cp     = make_float4(acc[i][0], acc[i][1], acc[i][2], acc[i][3]);
        *(float4*)(cp+4) = make_float4(acc[i][4], acc[i][5], acc[i][6], acc[i][7]);
    }
}

// -------------------- SwiGLU --------------------
__global__ void k_swiglu_moe() {
    int row = blockIdx.y;
    if (row >= g_off[En]) return;
    int j = blockIdx.x * 128 + threadIdx.x;
    float gv = g_gu[(size_t)row * F2n + j];
    float uv = g_gu[(size_t)row * F2n + Fn + j];
    g_act[(size_t)row * Fn + j] = gv / (1.f + expf(-gv)) * uv;
}
__global__ void k_swiglu_sh() {
    int row = blockIdx.y;
    int j = blockIdx.x * 128 + threadIdx.x;
    float gv = g_sgu[(size_t)row * FS2n + j];
    float uv = g_sgu[(size_t)row * FS2n + FSn + j];
    g_sact[(size_t)row * FSn + j] = gv / (1.f + expf(-gv)) * uv;
}

// -------------------- combine: weighted expert gather + gated shared expert ----
__global__ void k_combine(float* __restrict__ out) {
    int t = blockIdx.y;
    int h = blockIdx.x * 256 + threadIdx.x;
    float acc = g_gate[t] * g_sout[(size_t)t * Hn + h];
    #pragma unroll
    for (int k = 0; k < Kn; k++) {
        int i4 = t * Kn + k;
        acc = fmaf(g_rw[i4], g_eout[(size_t)g_row_id[i4] * Hn + h], acc);
    }
    out[(size_t)t * Hn + h] = acc;
}

// -------------------- launch --------------------
extern "C" void kernel_launch(void* const* d_in, const int* in_sizes, int n_in,
                              void* d_out, int out_size)
{
    const float* hs  = (const float*)d_in[0];
    const float* rw  = (const float*)d_in[1];
    const float* gup = (const float*)d_in[2];
    const float* dwn = (const float*)d_in[3];
    const float* sgu = (const float*)d_in[4];
    const float* sdn = (const float*)d_in[5];
    const float* sgw = (const float*)d_in[6];
    float* out = (float*)d_out;

    float *p_gu, *p_act, *p_eout, *p_sgu, *p_sact, *p_sout;
    cudaGetSymbolAddress((void**)&p_gu,   g_gu);
    cudaGetSymbolAddress((void**)&p_act,  g_act);
    cudaGetSymbolAddress((void**)&p_eout, g_eout);
    cudaGetSymbolAddress((void**)&p_sgu,  g_sgu);
    cudaGetSymbolAddress((void**)&p_sact, g_sact);
    cudaGetSymbolAddress((void**)&p_sout, g_sout);

    // routing + dispatch
    k_init<<<(RPAD + 255) / 256, 256>>>();
    k_router<<<Tn, 128>>>(hs, rw, sgw);
    k_scan<<<1, 1>>>();
    k_scatter<<<(Tn * Kn + 255) / 256, 256>>>();

    // expert path: gate_up -> SwiGLU -> down
    k_gemm<1><<<dim3(F2n / 128, RPAD / 128), 256>>>(hs,    gup, p_gu,   Hn, F2n);
    k_swiglu_moe<<<dim3(Fn / 128, RPAD), 128>>>();
    k_gemm<2><<<dim3(Hn  / 128, RPAD / 128), 256>>>(p_act, dwn, p_eout, Fn, Hn);

    // shared expert path
    k_gemm<0><<<dim3(FS2n / 128, Tn / 128), 256>>>(hs,     sgu, p_sgu,  Hn,  FS2n);
    k_swiglu_sh<<<dim3(FSn / 128, Tn), 128>>>();
    k_gemm<0><<<dim3(Hn   / 128, Tn / 128), 256>>>(p_sact, sdn, p_sout, FSn, Hn);

    // combine
    k_combine<<<dim3(Hn / 256, Tn), 256>>>(out);
}

// round 3
// speedup vs baseline: 2.7659x; 2.7659x over previous
#include <cuda_runtime.h>
#include <cuda.h>
#include <cuda_bf16.h>
#include <math.h>
#include <stdint.h>

// Problem constants
#define Tn   4096
#define Hn   2048
#define En   32
#define Kn   4
#define Fn   1408
#define F2n  2816
#define FSn  5632
#define FS2n 11264
#define RPAD (Tn*Kn + En*128)     // 20480 expanded rows, expert segs 128-aligned
#define MT_E (RPAD/128)           // 160 expert M-tiles

// ---------------- device scratch ----------------
__device__ __align__(1024) __nv_bfloat16 g_gupT_hi[(size_t)En*F2n*Hn];
__device__ __align__(1024) __nv_bfloat16 g_gupT_lo[(size_t)En*F2n*Hn];
__device__ __align__(1024) __nv_bfloat16 g_dwnT_hi[(size_t)En*Hn*Fn];
__device__ __align__(1024) __nv_bfloat16 g_dwnT_lo[(size_t)En*Hn*Fn];
__device__ __align__(1024) __nv_bfloat16 g_sguT_hi[(size_t)FS2n*Hn];
__device__ __align__(1024) __nv_bfloat16 g_sguT_lo[(size_t)FS2n*Hn];
__device__ __align__(1024) __nv_bfloat16 g_sdnT_hi[(size_t)Hn*FSn];
__device__ __align__(1024) __nv_bfloat16 g_sdnT_lo[(size_t)Hn*FSn];
__device__ __align__(1024) __nv_bfloat16 g_hid_hi[(size_t)Tn*Hn];
__device__ __align__(1024) __nv_bfloat16 g_hid_lo[(size_t)Tn*Hn];
__device__ __align__(1024) __nv_bfloat16 g_disp_hi[(size_t)RPAD*Hn];
__device__ __align__(1024) __nv_bfloat16 g_disp_lo[(size_t)RPAD*Hn];
__device__ __align__(1024) __nv_bfloat16 g_act_hi[(size_t)RPAD*Fn];
__device__ __align__(1024) __nv_bfloat16 g_act_lo[(size_t)RPAD*Fn];
__device__ __align__(1024) __nv_bfloat16 g_sact_hi[(size_t)Tn*FSn];
__device__ __align__(1024) __nv_bfloat16 g_sact_lo[(size_t)Tn*FSn];
__device__ float g_gu  [(size_t)RPAD * F2n];
__device__ float g_eout[(size_t)RPAD * Hn];
__device__ float g_sgu [(size_t)Tn * FS2n];
__device__ float g_sout[(size_t)Tn * Hn];
__device__ int   g_row_token[RPAD];
__device__ int   g_row_id[Tn*Kn];
__device__ float g_rw[Tn*Kn];
__device__ float g_gate[Tn];
__device__ int   g_cnt[En];
__device__ int   g_off[En+1];
__device__ int   g_pos[Tn*Kn];
__device__ int   g_eidx[Tn*Kn];
__device__ int   g_tile_expert[MT_E];

// ---------------- PTX helpers ----------------
__device__ __forceinline__ uint32_t s2u(const void* p) {
    uint32_t a;
    asm("{ .reg .u64 t; cvta.to.shared.u64 t, %1; cvt.u32.u64 %0, t; }" : "=r"(a) : "l"(p));
    return a;
}
#define MBARRIER_INIT(addr, cnt) \
    asm volatile("mbarrier.init.shared.b64 [%0], %1;" :: "r"((uint32_t)(addr)), "r"((uint32_t)(cnt)) : "memory")
#define MBARRIER_EXPECT_TX(addr, bytes) \
    asm volatile("mbarrier.arrive.expect_tx.shared.b64 _, [%0], %1;" :: "r"((uint32_t)(addr)), "r"((uint32_t)(bytes)) : "memory")
#define MBARRIER_ARRIVE(addr) \
    asm volatile("mbarrier.arrive.shared.b64 _, [%0];" :: "r"((uint32_t)(addr)) : "memory")
#define MBARRIER_WAIT_PARITY(mbar_smem_addr, phase_parity) do { \
    uint32_t _mbar = (uint32_t)(mbar_smem_addr); \
    uint32_t _parity = (uint32_t)(phase_parity); \
    uint32_t _done; \
    asm volatile("{\n\t.reg .pred p;\n\t" \
        "mbarrier.try_wait.parity.acquire.cta.shared::cta.b64 p, [%1], %2;\n\t" \
        "selp.b32 %0, 1, 0, p;\n\t}" \
        : "=r"(_done) : "r"(_mbar), "r"(_parity) : "memory"); \
    if (!_done) { \
        asm volatile("{\n\t.reg .pred P1;\n\t" \
            "WAIT_LOOP_%=:\n\t" \
            "mbarrier.try_wait.parity.acquire.cta.shared::cta.b64 P1, [%0], %1, 0x989680;\n\t" \
            "@P1 bra.uni WAIT_DONE_%=;\n\t" \
            "bra.uni WAIT_LOOP_%=;\n\t" \
            "WAIT_DONE_%=:\n\t}" \
            :: "r"(_mbar), "r"(_parity) : "memory"); \
    } \
} while(0)
#define FENCE_PROXY_ASYNC() asm volatile("fence.proxy.async.shared::cta;" ::: "memory")

__device__ __forceinline__ void tma3(uint32_t dst, const CUtensorMap* m,
                                     int cx, int cy, int cz, uint32_t mbar) {
    asm volatile(
        "cp.async.bulk.tensor.3d.shared::cta.global.tile.mbarrier::complete_tx::bytes "
        "[%0], [%1, {%2, %3, %4}], [%5];"
        :: "r"(dst), "l"(m), "r"(cx), "r"(cy), "r"(cz), "r"(mbar) : "memory");
}
__device__ __forceinline__ void ldsm4(uint32_t* q, uint32_t addr) {
    asm volatile("ldmatrix.sync.aligned.m8n8.x4.shared.b16 {%0,%1,%2,%3}, [%4];"
        : "=r"(q[0]), "=r"(q[1]), "=r"(q[2]), "=r"(q[3]) : "r"(addr));
}
__device__ __forceinline__ void mma16816(float* c, const uint32_t* a, uint32_t b0, uint32_t b1) {
    asm volatile("mma.sync.aligned.m16n8k16.row.col.f32.bf16.bf16.f32 "
        "{%0,%1,%2,%3}, {%4,%5,%6,%7}, {%8,%9}, {%0,%1,%2,%3};"
        : "+f"(c[0]), "+f"(c[1]), "+f"(c[2]), "+f"(c[3])
        : "r"(a[0]), "r"(a[1]), "r"(a[2]), "r"(a[3]), "r"(b0), "r"(b1));
}
__device__ __forceinline__ void split2(float v, __nv_bfloat16& h, __nv_bfloat16& l) {
    h = __float2bfloat16_rn(v);
    l = __float2bfloat16_rn(v - __bfloat162float(h));
}

// ---------------- routing ----------------
__global__ void k_init() {
    int i = blockIdx.x * blockDim.x + threadIdx.x;
    if (i < En)   g_cnt[i] = 0;
    if (i < RPAD) g_row_token[i] = -1;
}

__global__ void k_router(const float* __restrict__ hs, const float* __restrict__ rw,
                         const float* __restrict__ gw) {
    __shared__ float sh[Hn];
    __shared__ float slog[En];
    __shared__ float sred[128];
    int t = blockIdx.x;
    const float* hrow = hs + (size_t)t * Hn;
    for (int i = threadIdx.x; i < Hn; i += 128) sh[i] = hrow[i];
    __syncthreads();
    int warp = threadIdx.x >> 5, lane = threadIdx.x & 31;
    #pragma unroll
    for (int eo = 0; eo < 8; eo++) {
        int e = (warp << 3) + eo;
        const float* w = rw + (size_t)e * Hn;
        float acc = 0.f;
        for (int h = lane; h < Hn; h += 32) acc = fmaf(sh[h], w[h], acc);
        #pragma unroll
        for (int o = 16; o; o >>= 1) acc += __shfl_down_sync(0xffffffffu, acc, o);
        if (lane == 0) slog[e] = acc;
    }
    float g = 0.f;
    for (int h = threadIdx.x; h < Hn; h += 128) g = fmaf(sh[h], gw[h], g);
    sred[threadIdx.x] = g;
    __syncthreads();
    for (int s = 64; s; s >>= 1) {
        if (threadIdx.x < s) sred[threadIdx.x] += sred[threadIdx.x + s];
        __syncthreads();
    }
    if (threadIdx.x == 0) {
        g_gate[t] = 1.f / (1.f + expf(-sred[0]));
        float mx = slog[0];
        for (int e = 1; e < En; e++) mx = fmaxf(mx, slog[e]);
        float p[En]; float sum = 0.f;
        for (int e = 0; e < En; e++) { p[e] = expf(slog[e] - mx); sum += p[e]; }
        float inv = 1.f / sum;
        for (int k = 0; k < Kn; k++) {
            int best = 0; float bp = p[0];
            for (int e = 1; e < En; e++) if (p[e] > bp) { bp = p[e]; best = e; }
            int i4 = t * Kn + k;
            g_eidx[i4] = best;
            g_rw[i4]   = bp * inv;
            g_pos[i4]  = atomicAdd(&g_cnt[best], 1);
            p[best] = -1.f;
        }
    }
}

__global__ void k_scan() {
    int o = 0; g_off[0] = 0;
    for (int e = 0; e < En; e++) { o += ((g_cnt[e] + 127) & ~127); g_off[e+1] = o; }
    for (int t = 0; t < MT_E; t++) {
        int r = t * 128, e = -1;
        for (int x = 0; x < En; x++)
            if (r >= g_off[x] && r < g_off[x] + g_cnt[x]) { e = x; break; }
        g_tile_expert[t] = e;
    }
}

__global__ void k_scatter() {
    int i = blockIdx.x * blockDim.x + threadIdx.x;
    if (i >= Tn * Kn) return;
    int e = g_eidx[i];
    int row = g_off[e] + g_pos[i];
    g_row_token[row] = i >> 2;
    g_row_id[i] = row;
}

// ---------------- conversions ----------------
__global__ void k_tsplit(const float* __restrict__ W,
                         __nv_bfloat16* __restrict__ hi, __nv_bfloat16* __restrict__ lo,
                         int Kd, int Nd) {
    __shared__ float s[32][33];
    int e = blockIdx.z;
    const float* Wp = W + (size_t)e * Kd * Nd;
    int n0 = blockIdx.x * 32, k0 = blockIdx.y * 32;
    int tx = threadIdx.x, ty = threadIdx.y;
    #pragma unroll
    for (int j = 0; j < 4; j++)
        s[ty + 8*j][tx] = Wp[(size_t)(k0 + ty + 8*j) * Nd + n0 + tx];
    __syncthreads();
    size_t ob = (size_t)e * Nd * Kd;
    #pragma unroll
    for (int j = 0; j < 4; j++) {
        float v = s[tx][ty + 8*j];
        __nv_bfloat16 h, l; split2(v, h, l);
        size_t idx = ob + (size_t)(n0 + ty + 8*j) * Kd + k0 + tx;
        hi[idx] = h; lo[idx] = l;
    }
}

__global__ void k_split_hid(const float* __restrict__ hs) {
    int row = blockIdx.y;
    int c = blockIdx.x * 256 + threadIdx.x;
    float v = hs[(size_t)row * Hn + c];
    __nv_bfloat16 h, l; split2(v, h, l);
    g_hid_hi[(size_t)row * Hn + c] = h;
    g_hid_lo[(size_t)row * Hn + c] = l;
}

__global__ void k_gather_split(const float* __restrict__ hs) {
    int row = blockIdx.y;
    int c = blockIdx.x * 256 + threadIdx.x;
    int tok = g_row_token[row];
    float v = (tok >= 0) ? hs[(size_t)tok * Hn + c] : 0.f;
    __nv_bfloat16 h, l; split2(v, h, l);
    g_disp_hi[(size_t)row * Hn + c] = h;
    g_disp_lo[(size_t)row * Hn + c] = l;
}

// ---------------- SwiGLU ----------------
__global__ void k_swiglu_moe() {
    int row = blockIdx.y;
    if (g_tile_expert[row >> 7] < 0) return;
    int j = blockIdx.x * 128 + threadIdx.x;
    float gv = g_gu[(size_t)row * F2n + j];
    float uv = g_gu[(size_t)row * F2n + Fn + j];
    float a = gv / (1.f + expf(-gv)) * uv;
    __nv_bfloat16 h, l; split2(a, h, l);
    g_act_hi[(size_t)row * Fn + j] = h;
    g_act_lo[(size_t)row * Fn + j] = l;
}
__global__ void k_swiglu_sh() {
    int row = blockIdx.y;
    int j = blockIdx.x * 128 + threadIdx.x;
    float gv = g_sgu[(size_t)row * FS2n + j];
    float uv = g_sgu[(size_t)row * FS2n + FSn + j];
    float a = gv / (1.f + expf(-gv)) * uv;
    __nv_bfloat16 h, l; split2(a, h, l);
    g_sact_hi[(size_t)row * FSn + j] = h;
    g_sact_lo[(size_t)row * FSn + j] = l;
}

// ---------------- combine ----------------
__global__ void k_combine(float* __restrict__ out) {
    int t = blockIdx.y;
    int h = blockIdx.x * 256 + threadIdx.x;
    float acc = g_gate[t] * g_sout[(size_t)t * Hn + h];
    #pragma unroll
    for (int k = 0; k < Kn; k++) {
        int i4 = t * Kn + k;
        acc = fmaf(g_rw[i4], g_eout[(size_t)g_row_id[i4] * Hn + h], acc);
    }
    out[(size_t)t * Hn + h] = acc;
}

// ---------------- mma.sync bf16x3 GEMM: C[M,N] = (Ahi+Alo)(Bhi+Blo)^T ----------------
// CTA tile 128x128, K-chunk 64 (SW128 layout from TMA), 3-stage pipeline.
// 8 warps (2m x 4n), warp tile 64x32, mma.sync.m16n8k16 bf16, fp32 acc in regs.
#define STAGE_BYTES 65536
#define SMEM_CTRL   1024
#define GEMM_SMEM   (SMEM_CTRL + 3*STAGE_BYTES)

template<int GROUPED>
__global__ void __launch_bounds__(256, 1) k_mma(
    const __grid_constant__ CUtensorMap mAhi,
    const __grid_constant__ CUtensorMap mAlo,
    const __grid_constant__ CUtensorMap mBhi,
    const __grid_constant__ CUtensorMap mBlo,
    float* __restrict__ C, int Kdim, int Ncols)
{
    extern __shared__ __align__(1024) char smem[];
    const int mtile = blockIdx.y;
    int eid = 0;
    if (GROUPED) { eid = g_tile_expert[mtile]; if (eid < 0) return; }
    const int m0 = mtile * 128;
    const int n0 = blockIdx.x * 128;
    const int tid  = threadIdx.x;
    const int wid  = tid >> 5;
    const int lane = tid & 31;
    const int mw = (wid >> 2) * 64;   // warp m offset in tile
    const int nw = (wid & 3) * 32;    // warp n offset in tile
    const uint32_t sb = s2u(smem);
    // mbarriers: full[3] at sb+0..16, free[3] at sb+24..40
    if (tid == 0) {
        #pragma unroll
        for (int s = 0; s < 3; s++) {
            MBARRIER_INIT(sb + 8*s, 1);
            MBARRIER_INIT(sb + 24 + 8*s, 256);
        }
        FENCE_PROXY_ASYNC();
    }
    __syncthreads();

    const int nch = Kdim >> 6;
    const uint32_t st0 = sb + SMEM_CTRL;

    if (tid == 0) {
        #pragma unroll
        for (int c = 0; c < 3; c++) {
            uint32_t st = st0 + c * STAGE_BYTES;
            int kc = c << 6;
            MBARRIER_EXPECT_TX(sb + 8*c, STAGE_BYTES);
            tma3(st +     0, &mAhi, kc, m0, 0,   sb + 8*c);
            tma3(st + 16384, &mAlo, kc, m0, 0,   sb + 8*c);
            tma3(st + 32768, &mBhi, kc, n0, eid, sb + 8*c);
            tma3(st + 49152, &mBlo, kc, n0, eid, sb + 8*c);
        }
    }

    float acc[4][4][4];
    #pragma unroll
    for (int i = 0; i < 4; i++)
        #pragma unroll
        for (int j = 0; j < 4; j++)
            #pragma unroll
            for (int q = 0; q < 4; q++) acc[i][j][q] = 0.f;

    // ldmatrix per-lane addressing within SW128 tile:
    // addr = stage + rowsel*128 + ((c16 ^ (row&7)) << 4)
    const int r15 = lane & 15;       // row within 16-row tile
    const int cs  = lane >> 4;       // 16B-chunk select (k half)

    int s = 0, ph = 0;
    for (int c = 0; c < nch; c++) {
        MBARRIER_WAIT_PARITY(sb + 8*s, ph);
        const uint32_t st = st0 + s * STAGE_BYTES;
        #pragma unroll
        for (int kk = 0; kk < 4; kk++) {
            uint32_t aH[16], aL[16], bH[8], bL[8];
            #pragma unroll
            for (int mi = 0; mi < 4; mi++) {
                int row = mw + mi * 16 + r15;
                uint32_t off = row * 128 + ((((kk << 1) | cs) ^ (row & 7)) << 4);
                ldsm4(aH + 4*mi, st + off);
                ldsm4(aL + 4*mi, st + 16384 + off);
            }
            #pragma unroll
            for (int nj = 0; nj < 2; nj++) {
                int row = nw + nj * 16 + r15;
                uint32_t off = row * 128 + ((((kk << 1) | cs) ^ (row & 7)) << 4);
                ldsm4(bH + 4*nj, st + 32768 + off);
                ldsm4(bL + 4*nj, st + 49152 + off);
            }
            #pragma unroll
            for (int mi = 0; mi < 4; mi++) {
                #pragma unroll
                for (int ni = 0; ni < 4; ni++) {
                    int nj = ni >> 1, hf = ni & 1;
                    uint32_t bh0 = bH[4*nj + hf], bh1 = bH[4*nj + 2 + hf];
                    uint32_t bl0 = bL[4*nj + hf], bl1 = bL[4*nj + 2 + hf];
                    mma16816(acc[mi][ni], aH + 4*mi, bh0, bh1);
                    mma16816(acc[mi][ni], aH + 4*mi, bl0, bl1);
                    mma16816(acc[mi][ni], aL + 4*mi, bh0, bh1);
                }
            }
        }
        MBARRIER_ARRIVE(sb + 24 + 8*s);
        if (tid == 0 && c + 3 < nch) {
            MBARRIER_WAIT_PARITY(sb + 24 + 8*s, ph);  // all warps done with stage s
            int kc = (c + 3) << 6;
            MBARRIER_EXPECT_TX(sb + 8*s, STAGE_BYTES);
            tma3(st +     0, &mAhi, kc, m0, 0,   sb + 8*s);
            tma3(st + 16384, &mAlo, kc, m0, 0,   sb + 8*s);
            tma3(st + 32768, &mBhi, kc, n0, eid, sb + 8*s);
            tma3(st + 49152, &mBlo, kc, n0, eid, sb + 8*s);
        }
        if (++s == 3) { s = 0; ph ^= 1; }
    }

    // epilogue: direct fp32 stores, frag layout m16n8
    const int er = lane >> 2;          // row within 8
    const int ec = (lane & 3) << 1;    // col pair
    #pragma unroll
    for (int mi = 0; mi < 4; mi++) {
        #pragma unroll
        for (int ni = 0; ni < 4; ni++) {
            size_t row = (size_t)(m0 + mw + mi * 16 + er);
            size_t col = (size_t)(n0 + nw + ni * 8 + ec);
            *(float2*)(C + row * Ncols + col)       = make_float2(acc[mi][ni][0], acc[mi][ni][1]);
            *(float2*)(C + (row + 8) * Ncols + col) = make_float2(acc[mi][ni][2], acc[mi][ni][3]);
        }
    }
}

// ---------------- host launch ----------------
typedef CUresult (*encode_fn_t)(CUtensorMap*, CUtensorMapDataType, cuuint32_t, void*,
                                const cuuint64_t*, const cuuint64_t*, const cuuint32_t*,
                                const cuuint32_t*, CUtensorMapInterleave, CUtensorMapSwizzle,
                                CUtensorMapL2promotion, CUtensorMapFloatOOBfill);

static void mkmap(encode_fn_t enc, CUtensorMap* m, void* ptr,
                  uint64_t d0, uint64_t d1, uint64_t d2) {
    cuuint64_t dims[3] = {d0, d1, d2};
    cuuint64_t str[2]  = {d0 * 2, d0 * d1 * 2};
    cuuint32_t box[3]  = {64, 128, 1};
    cuuint32_t es[3]   = {1, 1, 1};
    enc(m, CU_TENSOR_MAP_DATA_TYPE_BFLOAT16, 3, ptr, dims, str, box, es,
        CU_TENSOR_MAP_INTERLEAVE_NONE, CU_TENSOR_MAP_SWIZZLE_128B,
        CU_TENSOR_MAP_L2_PROMOTION_L2_128B, CU_TENSOR_MAP_FLOAT_OOB_FILL_NONE);
}

extern "C" void kernel_launch(void* const* d_in, const int* in_sizes, int n_in,
                              void* d_out, int out_size)
{
    const float* hs  = (const float*)d_in[0];
    const float* rw  = (const float*)d_in[1];
    const float* gup = (const float*)d_in[2];
    const float* dwn = (const float*)d_in[3];
    const float* sgu = (const float*)d_in[4];
    const float* sdn = (const float*)d_in[5];
    const float* sgw = (const float*)d_in[6];
    float* out = (float*)d_out;

    void* fp = nullptr;
    cudaDriverEntryPointQueryResult qr;
    cudaGetDriverEntryPointByVersion("cuTensorMapEncodeTiled", &fp, 12000,
                                     cudaEnableDefault, &qr);
    encode_fn_t enc = (encode_fn_t)fp;

    void *p_gupT_hi, *p_gupT_lo, *p_dwnT_hi, *p_dwnT_lo, *p_sguT_hi, *p_sguT_lo,
         *p_sdnT_hi, *p_sdnT_lo, *p_hid_hi, *p_hid_lo, *p_disp_hi, *p_disp_lo,
         *p_act_hi, *p_act_lo, *p_sact_hi, *p_sact_lo;
    float *p_gu, *p_eout, *p_sgu, *p_sout;
    cudaGetSymbolAddress(&p_gupT_hi, g_gupT_hi); cudaGetSymbolAddress(&p_gupT_lo, g_gupT_lo);
    cudaGetSymbolAddress(&p_dwnT_hi, g_dwnT_hi); cudaGetSymbolAddress(&p_dwnT_lo, g_dwnT_lo);
    cudaGetSymbolAddress(&p_sguT_hi, g_sguT_hi); cudaGetSymbolAddress(&p_sguT_lo, g_sguT_lo);
    cudaGetSymbolAddress(&p_sdnT_hi, g_sdnT_hi); cudaGetSymbolAddress(&p_sdnT_lo, g_sdnT_lo);
    cudaGetSymbolAddress(&p_hid_hi,  g_hid_hi);  cudaGetSymbolAddress(&p_hid_lo,  g_hid_lo);
    cudaGetSymbolAddress(&p_disp_hi, g_disp_hi); cudaGetSymbolAddress(&p_disp_lo, g_disp_lo);
    cudaGetSymbolAddress(&p_act_hi,  g_act_hi);  cudaGetSymbolAddress(&p_act_lo,  g_act_lo);
    cudaGetSymbolAddress(&p_sact_hi, g_sact_hi); cudaGetSymbolAddress(&p_sact_lo, g_sact_lo);
    cudaGetSymbolAddress((void**)&p_gu,   g_gu);
    cudaGetSymbolAddress((void**)&p_eout, g_eout);
    cudaGetSymbolAddress((void**)&p_sgu,  g_sgu);
    cudaGetSymbolAddress((void**)&p_sout, g_sout);

    CUtensorMap mDispHi, mDispLo, mGupHi, mGupLo;
    CUtensorMap mActHi,  mActLo,  mDwnHi, mDwnLo;
    CUtensorMap mHidHi,  mHidLo,  mSguHi, mSguLo;
    CUtensorMap mSactHi, mSactLo, mSdnHi, mSdnLo;
    mkmap(enc, &mDispHi, p_disp_hi, Hn,  RPAD, 1);
    mkmap(enc, &mDispLo, p_disp_lo, Hn,  RPAD, 1);
    mkmap(enc, &mGupHi,  p_gupT_hi, Hn,  F2n,  En);
    mkmap(enc, &mGupLo,  p_gupT_lo, Hn,  F2n,  En);
    mkmap(enc, &mActHi,  p_act_hi,  Fn,  RPAD, 1);
    mkmap(enc, &mActLo,  p_act_lo,  Fn,  RPAD, 1);
    mkmap(enc, &mDwnHi,  p_dwnT_hi, Fn,  Hn,   En);
    mkmap(enc, &mDwnLo,  p_dwnT_lo, Fn,  Hn,   En);
    mkmap(enc, &mHidHi,  p_hid_hi,  Hn,  Tn,   1);
    mkmap(enc, &mHidLo,  p_hid_lo,  Hn,  Tn,   1);
    mkmap(enc, &mSguHi,  p_sguT_hi, Hn,  FS2n, 1);
    mkmap(enc, &mSguLo,  p_sguT_lo, Hn,  FS2n, 1);
    mkmap(enc, &mSactHi, p_sact_hi, FSn, Tn,   1);
    mkmap(enc, &mSactLo, p_sact_lo, FSn, Tn,   1);
    mkmap(enc, &mSdnHi,  p_sdnT_hi, FSn, Hn,   1);
    mkmap(enc, &mSdnLo,  p_sdnT_lo, FSn, Hn,   1);

    cudaFuncSetAttribute(k_mma<0>, cudaFuncAttributeMaxDynamicSharedMemorySize, GEMM_SMEM);
    cudaFuncSetAttribute(k_mma<1>, cudaFuncAttributeMaxDynamicSharedMemorySize, GEMM_SMEM);

    // routing + dispatch
    k_init<<<(RPAD + 255) / 256, 256>>>();
    k_router<<<Tn, 128>>>(hs, rw, sgw);
    k_scan<<<1, 1>>>();
    k_scatter<<<(Tn * Kn + 255) / 256, 256>>>();

    // conversions
    dim3 tb(32, 8);
    k_tsplit<<<dim3(F2n/32,  Hn/32,  En), tb>>>(gup, (__nv_bfloat16*)p_gupT_hi, (__nv_bfloat16*)p_gupT_lo, Hn,  F2n);
    k_tsplit<<<dim3(Hn/32,   Fn/32,  En), tb>>>(dwn, (__nv_bfloat16*)p_dwnT_hi, (__nv_bfloat16*)p_dwnT_lo, Fn,  Hn);
    k_tsplit<<<dim3(FS2n/32, Hn/32,  1 ), tb>>>(sgu, (__nv_bfloat16*)p_sguT_hi, (__nv_bfloat16*)p_sguT_lo, Hn,  FS2n);
    k_tsplit<<<dim3(Hn/32,   FSn/32, 1 ), tb>>>(sdn, (__nv_bfloat16*)p_sdnT_hi, (__nv_bfloat16*)p_sdnT_lo, FSn, Hn);
    k_split_hid<<<dim3(Hn/256, Tn), 256>>>(hs);
    k_gather_split<<<dim3(Hn/256, RPAD), 256>>>(hs);

    // expert path
    k_mma<1><<<dim3(F2n/128, MT_E), 256, GEMM_SMEM>>>(mDispHi, mDispLo, mGupHi, mGupLo, p_gu,   Hn, F2n);
    k_swiglu_moe<<<dim3(Fn/128, RPAD), 128>>>();
    k_mma<1><<<dim3(Hn/128,  MT_E), 256, GEMM_SMEM>>>(mActHi,  mActLo,  mDwnHi, mDwnLo, p_eout, Fn, Hn);

    // shared expert path
    k_mma<0><<<dim3(FS2n/128, Tn/128), 256, GEMM_SMEM>>>(mHidHi,  mHidLo,  mSguHi, mSguLo, p_sgu,  Hn,  FS2n);
    k_swiglu_sh<<<dim3(FSn/128, Tn), 128>>>();
    k_mma<0><<<dim3(Hn/128,   Tn/128), 256, GEMM_SMEM>>>(mSactHi, mSactLo, mSdnHi, mSdnLo, p_sout, FSn, Hn);

    // combine
    k_combine<<<dim3(Hn/256, Tn), 256>>>(out);
}